// round 15
// baseline (speedup 1.0000x reference)
#include <cuda_runtime.h>
#include <cuda_bf16.h>
#include <cstdint>

// Shapes (fixed for this problem)
#define B_  2
#define T_  2048
#define C_  2048          // d_model
#define H_  16
#define DH_ 128           // head dim
#define BT_ (B_ * T_)     // 4096 rows
#define QKV_C (3 * C_)    // 6144

// ---------------------------------------------------------------------------
// Scratch (device globals — no allocation)
// ---------------------------------------------------------------------------
__device__ float g_qkv[(size_t)BT_ * QKV_C];                 // 96 MB fp32
__device__ __nv_bfloat16 g_qkvhi[(size_t)BT_ * QKV_C];       // 48 MB
__device__ __nv_bfloat16 g_qkvlo[(size_t)BT_ * QKV_C];       // 48 MB
__device__ __nv_bfloat16 g_xhi[(size_t)BT_ * C_];
__device__ __nv_bfloat16 g_xlo[(size_t)BT_ * C_];
__device__ __nv_bfloat16 g_wqkvhi[(size_t)QKV_C * C_];
__device__ __nv_bfloat16 g_wqkvlo[(size_t)QKV_C * C_];
__device__ __nv_bfloat16 g_wprojhi[(size_t)C_ * C_];
__device__ __nv_bfloat16 g_wprojlo[(size_t)C_ * C_];
__device__ __nv_bfloat16 g_yhi[(size_t)BT_ * C_];
__device__ __nv_bfloat16 g_ylo[(size_t)BT_ * C_];

// ---------------------------------------------------------------------------
// PTX helpers (portable sm_80-level ISA only — harness emits compute_103)
// ---------------------------------------------------------------------------
__device__ __forceinline__ uint32_t smem_u32(const void* p) {
    uint32_t a;
    asm("{ .reg .u64 t; cvta.to.shared.u64 t, %1; cvt.u32.u64 %0, t; }"
        : "=r"(a) : "l"(p));
    return a;
}

#define CP16(dst, src) \
    asm volatile("cp.async.cg.shared.global [%0], [%1], 16;" \
                 :: "r"(dst), "l"(src) : "memory")
#define CP_COMMIT() asm volatile("cp.async.commit_group;" ::: "memory")

#define LDSM4(r, addr) \
    asm volatile("ldmatrix.sync.aligned.m8n8.x4.shared.b16 {%0,%1,%2,%3}, [%4];" \
                 : "=r"((r)[0]), "=r"((r)[1]), "=r"((r)[2]), "=r"((r)[3]) \
                 : "r"(addr))

#define LDSM4T(r, addr) \
    asm volatile("ldmatrix.sync.aligned.m8n8.x4.trans.shared.b16 {%0,%1,%2,%3}, [%4];" \
                 : "=r"((r)[0]), "=r"((r)[1]), "=r"((r)[2]), "=r"((r)[3]) \
                 : "r"(addr))

#define LDSM2(r, addr) \
    asm volatile("ldmatrix.sync.aligned.m8n8.x2.shared.b16 {%0,%1}, [%2];" \
                 : "=r"((r)[0]), "=r"((r)[1]) \
                 : "r"(addr))

#define MMA_BF16(d, a, b) \
    asm volatile("mma.sync.aligned.m16n8k16.row.col.f32.bf16.bf16.f32 " \
                 "{%0,%1,%2,%3}, {%4,%5,%6,%7}, {%8,%9}, {%0,%1,%2,%3};" \
                 : "+f"((d)[0]), "+f"((d)[1]), "+f"((d)[2]), "+f"((d)[3]) \
                 : "r"((a)[0]), "r"((a)[1]), "r"((a)[2]), "r"((a)[3]), \
                   "r"((b)[0]), "r"((b)[1]))

// fast exp2 for x <= 0: degree-5 poly, rel err < 1e-4, no MUFU
__device__ __forceinline__ float exp2_fast(float x) {
    x = fmaxf(x, -80.f);
    float fl = floorf(x);
    float fr = x - fl;
    float p = fmaf(fr, 0.00133335581f, 0.00961812910f);
    p = fmaf(fr, p, 0.0555041089f);
    p = fmaf(fr, p, 0.240226512f);
    p = fmaf(fr, p, 0.693147182f);
    p = fmaf(fr, p, 1.0f);
    int e = (int)fl;
    return __int_as_float((e + 127) << 23) * p;
}

// ---------------------------------------------------------------------------
// Decompose fp32 -> bf16 hi + bf16 lo (elementwise, float4-vectorized)
// ---------------------------------------------------------------------------
__global__ void decompose_hi_lo(const float* __restrict__ in,
                                __nv_bfloat16* __restrict__ hi,
                                __nv_bfloat16* __restrict__ lo, int n4) {
    int i = blockIdx.x * 256 + threadIdx.x;
    if (i >= n4) return;
    float4 v = ((const float4*)in)[i];
    __nv_bfloat162 h0 = __floats2bfloat162_rn(v.x, v.y);
    __nv_bfloat162 h1 = __floats2bfloat162_rn(v.z, v.w);
    float2 f0 = __bfloat1622float2(h0);
    float2 f1 = __bfloat1622float2(h1);
    __nv_bfloat162 l0 = __floats2bfloat162_rn(v.x - f0.x, v.y - f0.y);
    __nv_bfloat162 l1 = __floats2bfloat162_rn(v.z - f1.x, v.w - f1.y);
    ((__nv_bfloat162*)hi)[i * 2 + 0] = h0;
    ((__nv_bfloat162*)hi)[i * 2 + 1] = h1;
    ((__nv_bfloat162*)lo)[i * 2 + 0] = l0;
    ((__nv_bfloat162*)lo)[i * 2 + 1] = l1;
}

// ---------------------------------------------------------------------------
// HMMA GEMM: C[M,N] = (Ahi+Alo)[M,K] @ (Bhi+Blo)[N,K]^T, fp32 out.
// (unchanged from R12)
// ---------------------------------------------------------------------------
#define GBM 128
#define GBN 128
#define GBK 32
#define ASTR 40
#define ARR_B (128 * ASTR * 2)
#define STAGE_B (4 * ARR_B)
#define NSTAGE 4
#define GEMM_SMEM (NSTAGE * STAGE_B)

__global__ __launch_bounds__(256, 1)
void gemm_bf16x2(const __nv_bfloat16* __restrict__ Ahi,
                 const __nv_bfloat16* __restrict__ Alo,
                 const __nv_bfloat16* __restrict__ Bhi,
                 const __nv_bfloat16* __restrict__ Blo,
                 float* __restrict__ C, int M, int N, int K) {
    extern __shared__ char gsm[];
    const uint32_t sbase = smem_u32(gsm);
    const int tid = threadIdx.x;
    const int wid = tid >> 5, lid = tid & 31;
    const int warp_m = wid >> 2;
    const int warp_n = wid & 3;
    const int bm = blockIdx.y * GBM;
    const int bn = blockIdx.x * GBN;

    const __nv_bfloat16* src[8];
    uint32_t dstoff[8];
    #pragma unroll
    for (int i = 0; i < 8; i++) {
        int cid = tid + i * 256;
        int arr = cid >> 9;
        int rem = cid & 511;
        int row = rem >> 2;
        int q   = rem & 3;
        const __nv_bfloat16* base =
            (arr == 0) ? Ahi + (size_t)(bm + row) * K :
            (arr == 1) ? Alo + (size_t)(bm + row) * K :
            (arr == 2) ? Bhi + (size_t)(bn + row) * K :
                         Blo + (size_t)(bn + row) * K;
        src[i] = base + q * 8;
        dstoff[i] = (uint32_t)(arr * ARR_B + row * (ASTR * 2) + q * 16);
    }

    const int r8 = lid & 7;
    uint32_t aoff[4], boff[4];
    #pragma unroll
    for (int mi = 0; mi < 4; mi++)
        aoff[mi] = (uint32_t)((warp_m * 64 + mi * 16 + r8 + ((lid >> 3) & 1) * 8)
                              * (ASTR * 2) + ((lid >> 4) & 1) * 16);
    #pragma unroll
    for (int ni = 0; ni < 4; ni++)
        boff[ni] = (uint32_t)((warp_n * 32 + ni * 8 + r8)
                              * (ASTR * 2) + ((lid >> 3) & 1) * 16);

    float acc[4][4][4];
    #pragma unroll
    for (int mi = 0; mi < 4; mi++)
        #pragma unroll
        for (int ni = 0; ni < 4; ni++)
            #pragma unroll
            for (int e = 0; e < 4; e++) acc[mi][ni][e] = 0.f;

    const int nch = K / GBK;

    #pragma unroll
    for (int s = 0; s < NSTAGE - 1; s++) {
        if (s < nch) {
            uint32_t sb = sbase + s * STAGE_B;
            #pragma unroll
            for (int i = 0; i < 8; i++)
                CP16(sb + dstoff[i], src[i] + s * GBK);
        }
        CP_COMMIT();
    }

    for (int c = 0; c < nch; c++) {
        asm volatile("cp.async.wait_group 2;" ::: "memory");
        __syncthreads();

        {
            int s = c + NSTAGE - 1;
            if (s < nch) {
                uint32_t sb = sbase + (s & (NSTAGE - 1)) * STAGE_B;
                #pragma unroll
                for (int i = 0; i < 8; i++)
                    CP16(sb + dstoff[i], src[i] + (size_t)s * GBK);
            }
            CP_COMMIT();
        }

        const uint32_t sb = sbase + (c & (NSTAGE - 1)) * STAGE_B;
        #pragma unroll
        for (int ks = 0; ks < 2; ks++) {
            uint32_t ah[4][4], al[4][4], bh[4][2], bl[4][2];
            #pragma unroll
            for (int mi = 0; mi < 4; mi++) {
                LDSM4(ah[mi], sb + 0 * ARR_B + aoff[mi] + ks * 32);
                LDSM4(al[mi], sb + 1 * ARR_B + aoff[mi] + ks * 32);
            }
            #pragma unroll
            for (int ni = 0; ni < 4; ni++) {
                LDSM2(bh[ni], sb + 2 * ARR_B + boff[ni] + ks * 32);
                LDSM2(bl[ni], sb + 3 * ARR_B + boff[ni] + ks * 32);
            }
            #pragma unroll
            for (int mi = 0; mi < 4; mi++)
                #pragma unroll
                for (int ni = 0; ni < 4; ni++) {
                    MMA_BF16(acc[mi][ni], ah[mi], bh[ni]);
                    MMA_BF16(acc[mi][ni], ah[mi], bl[ni]);
                    MMA_BF16(acc[mi][ni], al[mi], bh[ni]);
                }
        }
    }

    const int g = lid >> 2, t4 = lid & 3;
    #pragma unroll
    for (int mi = 0; mi < 4; mi++) {
        int row = bm + warp_m * 64 + mi * 16 + g;
        #pragma unroll
        for (int ni = 0; ni < 4; ni++) {
            int col = bn + warp_n * 32 + ni * 8 + 2 * t4;
            *(float2*)(C + (size_t)row * N + col) =
                make_float2(acc[mi][ni][0], acc[mi][ni][1]);
            *(float2*)(C + (size_t)(row + 8) * N + col) =
                make_float2(acc[mi][ni][2], acc[mi][ni][3]);
        }
    }
}

// ---------------------------------------------------------------------------
// Tensor-core flash attention (causal), bf16 hi/lo 3-pass for QK^T and PV.
// CTA: 128 Q rows x 1 head; 8 warps x 16 rows; K/V tiles 64 rows,
// 2-stage cp.async pipeline; S fragments reused as P A-fragments (FA2).
// ---------------------------------------------------------------------------
#define FQR 128
#define FKR 64
#define FSTR_B 272                       // smem row stride bytes (136 bf16)
#define FARR_B (FKR * FSTR_B)            // 17408 B per array
#define FSTAGE_B (4 * FARR_B)            // 69632 B (Khi,Klo,Vhi,Vlo)
#define FLASH_SMEM (2 * FSTAGE_B)        // 139264 B

#define CLOG2 0.12751744f                // (1/sqrt(128)) * log2(e)

__global__ __launch_bounds__(256, 1)
void flash_attn_mma(const __nv_bfloat16* __restrict__ qkvhi,
                    const __nv_bfloat16* __restrict__ qkvlo,
                    __nv_bfloat16* __restrict__ yhi,
                    __nv_bfloat16* __restrict__ ylo) {
    extern __shared__ char fsmc[];
    const uint32_t sb0 = smem_u32(fsmc);
    const int qt = gridDim.x - 1 - blockIdx.x;   // big tiles first
    const int h = blockIdx.y, b = blockIdx.z;
    const int tid = threadIdx.x, wid = tid >> 5, lid = tid & 31;
    const int t8 = lid >> 3, l7 = lid & 7;

    const size_t rowbase = (size_t)(b * T_) * QKV_C + h * DH_;

    // ---- load Q tile (hi/lo) into stage-0 area ----
    #pragma unroll
    for (int i = 0; i < 16; i++) {
        int cid = tid + i * 256;
        int arr = cid >> 11;                  // 0 hi, 1 lo
        int rem = cid & 2047;
        int row = rem >> 4, q = rem & 15;
        const __nv_bfloat16* s = (arr ? qkvlo : qkvhi)
            + rowbase + (size_t)(qt * FQR + row) * QKV_C + q * 8;
        CP16(sb0 + arr * 34816 + row * FSTR_B + q * 16, s);
    }
    CP_COMMIT();
    asm volatile("cp.async.wait_group 0;" ::: "memory");
    __syncthreads();

    // ---- Q fragments -> registers ----
    uint32_t qh[8][4], qlr[8][4];
    {
        uint32_t lanebase = (uint32_t)((wid * 16 + (t8 & 1) * 8 + l7) * FSTR_B
                                       + (t8 >> 1) * 16);
        #pragma unroll
        for (int kk = 0; kk < 8; kk++) {
            LDSM4(qh[kk],  sb0 + lanebase + kk * 32);
            LDSM4(qlr[kk], sb0 + 34816 + lanebase + kk * 32);
        }
    }
    __syncthreads();

    auto issue_tile = [&](int kt, uint32_t stg) {
        #pragma unroll
        for (int i = 0; i < 16; i++) {
            int cid = tid + i * 256;
            int arr = cid >> 10;              // 0 Khi 1 Klo 2 Vhi 3 Vlo
            int rem = cid & 1023;
            int row = rem >> 4, q = rem & 15;
            const __nv_bfloat16* base = (arr & 1) ? qkvlo : qkvhi;
            int koff = (arr >> 1) ? 2 * C_ : C_;
            const __nv_bfloat16* s = base + rowbase + koff
                + (size_t)(kt * FKR + row) * QKV_C + q * 8;
            CP16(stg + arr * FARR_B + row * FSTR_B + q * 16, s);
        }
        CP_COMMIT();
    };

    float oacc[16][4];
    #pragma unroll
    for (int dn = 0; dn < 16; dn++)
        #pragma unroll
        for (int e = 0; e < 4; e++) oacc[dn][e] = 0.f;
    float m0 = -1e30f, m1 = -1e30f, l0 = 0.f, l1 = 0.f;

    const int g = lid >> 2;
    const int qr0 = qt * FQR + wid * 16 + g;
    const int qr1 = qr0 + 8;
    const int wrmax = qt * FQR + wid * 16 + 15;
    const uint32_t kbase = (uint32_t)(((t8 >> 1) * 8 + l7) * FSTR_B + (t8 & 1) * 16);
    const uint32_t vbase = (uint32_t)(((t8 & 1) * 8 + l7) * FSTR_B + (t8 >> 1) * 16);

    const int nkt = 2 * qt + 2;
    issue_tile(0, sb0);

    for (int kt = 0; kt < nkt; kt++) {
        const uint32_t stage = sb0 + (kt & 1) * FSTAGE_B;
        if (kt + 1 < nkt) {
            issue_tile(kt + 1, sb0 + ((kt + 1) & 1) * FSTAGE_B);
            asm volatile("cp.async.wait_group 1;" ::: "memory");
        } else {
            asm volatile("cp.async.wait_group 0;" ::: "memory");
        }
        __syncthreads();

        if (kt * FKR <= wrmax) {   // warp-uniform: skip fully-masked tiles
            // ---- S = Q K^T (hi*hi + hi*lo + lo*hi) ----
            float sacc[8][4];
            #pragma unroll
            for (int nt = 0; nt < 8; nt++)
                #pragma unroll
                for (int e = 0; e < 4; e++) sacc[nt][e] = 0.f;

            const uint32_t Kh = stage, Kl = stage + FARR_B;
            #pragma unroll
            for (int kk = 0; kk < 8; kk++) {
                #pragma unroll
                for (int ntp = 0; ntp < 4; ntp++) {
                    uint32_t khf[4], klf[4];
                    LDSM4(khf, Kh + ntp * (16 * FSTR_B) + kbase + kk * 32);
                    LDSM4(klf, Kl + ntp * (16 * FSTR_B) + kbase + kk * 32);
                    MMA_BF16(sacc[2 * ntp],     qh[kk],  &khf[0]);
                    MMA_BF16(sacc[2 * ntp],     qh[kk],  &klf[0]);
                    MMA_BF16(sacc[2 * ntp],     qlr[kk], &khf[0]);
                    MMA_BF16(sacc[2 * ntp + 1], qh[kk],  &khf[2]);
                    MMA_BF16(sacc[2 * ntp + 1], qh[kk],  &klf[2]);
                    MMA_BF16(sacc[2 * ntp + 1], qlr[kk], &khf[2]);
                }
            }

            // ---- causal mask ----
            if (kt * FKR + FKR - 1 > qr0) {
                #pragma unroll
                for (int nt = 0; nt < 8; nt++) {
                    int col = kt * FKR + nt * 8 + 2 * (lid & 3);
                    if (col     > qr0) sacc[nt][0] = -1e30f;
                    if (col + 1 > qr0) sacc[nt][1] = -1e30f;
                    if (col     > qr1) sacc[nt][2] = -1e30f;
                    if (col + 1 > qr1) sacc[nt][3] = -1e30f;
                }
            }

            // ---- online softmax (per-warp, register-resident) ----
            float rm0 = -1e30f, rm1 = -1e30f;
            #pragma unroll
            for (int nt = 0; nt < 8; nt++) {
                rm0 = fmaxf(rm0, fmaxf(sacc[nt][0], sacc[nt][1]));
                rm1 = fmaxf(rm1, fmaxf(sacc[nt][2], sacc[nt][3]));
            }
            #pragma unroll
            for (int d = 1; d < 4; d <<= 1) {
                rm0 = fmaxf(rm0, __shfl_xor_sync(0xFFFFFFFFu, rm0, d));
                rm1 = fmaxf(rm1, __shfl_xor_sync(0xFFFFFFFFu, rm1, d));
            }
            float m0n = fmaxf(m0, rm0), m1n = fmaxf(m1, rm1);
            float rs0 = exp2_fast((m0 - m0n) * CLOG2);
            float rs1 = exp2_fast((m1 - m1n) * CLOG2);
            m0 = m0n; m1 = m1n;

            float ls0 = 0.f, ls1 = 0.f;
            uint32_t pha[8][2], pla[8][2];
            #pragma unroll
            for (int nt = 0; nt < 8; nt++) {
                float p0 = exp2_fast((sacc[nt][0] - m0) * CLOG2);
                float p1 = exp2_fast((sacc[nt][1] - m0) * CLOG2);
                float p2 = exp2_fast((sacc[nt][2] - m1) * CLOG2);
                float p3 = exp2_fast((sacc[nt][3] - m1) * CLOG2);
                ls0 += p0 + p1; ls1 += p2 + p3;
                __nv_bfloat162 h01 = __floats2bfloat162_rn(p0, p1);
                __nv_bfloat162 h23 = __floats2bfloat162_rn(p2, p3);
                float2 f01 = __bfloat1622float2(h01);
                float2 f23 = __bfloat1622float2(h23);
                __nv_bfloat162 lo01 = __floats2bfloat162_rn(p0 - f01.x, p1 - f01.y);
                __nv_bfloat162 lo23 = __floats2bfloat162_rn(p2 - f23.x, p3 - f23.y);
                pha[nt][0] = *(uint32_t*)&h01;  pha[nt][1] = *(uint32_t*)&h23;
                pla[nt][0] = *(uint32_t*)&lo01; pla[nt][1] = *(uint32_t*)&lo23;
            }
            #pragma unroll
            for (int d = 1; d < 4; d <<= 1) {
                ls0 += __shfl_xor_sync(0xFFFFFFFFu, ls0, d);
                ls1 += __shfl_xor_sync(0xFFFFFFFFu, ls1, d);
            }
            l0 = l0 * rs0 + ls0;
            l1 = l1 * rs1 + ls1;

            #pragma unroll
            for (int dn = 0; dn < 16; dn++) {
                oacc[dn][0] *= rs0; oacc[dn][1] *= rs0;
                oacc[dn][2] *= rs1; oacc[dn][3] *= rs1;
            }

            // ---- O += P V (hi*hi + lo*hi + hi*lo) ----
            const uint32_t Vh = stage + 2 * FARR_B, Vl = stage + 3 * FARR_B;
            #pragma unroll
            for (int ks = 0; ks < 4; ks++) {
                uint32_t aH[4] = {pha[2 * ks][0], pha[2 * ks][1],
                                  pha[2 * ks + 1][0], pha[2 * ks + 1][1]};
                uint32_t aL[4] = {pla[2 * ks][0], pla[2 * ks][1],
                                  pla[2 * ks + 1][0], pla[2 * ks + 1][1]};
                #pragma unroll
                for (int dtp = 0; dtp < 8; dtp++) {
                    uint32_t vhf[4], vlf[4];
                    LDSM4T(vhf, Vh + ks * (16 * FSTR_B) + vbase + dtp * 32);
                    LDSM4T(vlf, Vl + ks * (16 * FSTR_B) + vbase + dtp * 32);
                    MMA_BF16(oacc[2 * dtp],     aH, &vhf[0]);
                    MMA_BF16(oacc[2 * dtp],     aL, &vhf[0]);
                    MMA_BF16(oacc[2 * dtp],     aH, &vlf[0]);
                    MMA_BF16(oacc[2 * dtp + 1], aH, &vhf[2]);
                    MMA_BF16(oacc[2 * dtp + 1], aL, &vhf[2]);
                    MMA_BF16(oacc[2 * dtp + 1], aH, &vlf[2]);
                }
            }
        }
        __syncthreads();
    }

    // ---- epilogue: normalize, decompose to bf16 hi/lo, store ----
    float inv0 = 1.f / l0, inv1 = 1.f / l1;
    size_t r0 = (size_t)(b * T_ + qt * FQR + wid * 16 + g) * C_
                + h * DH_ + 2 * (lid & 3);
    size_t r1 = r0 + 8 * (size_t)C_;
    #pragma unroll
    for (int dn = 0; dn < 16; dn++) {
        float a0 = oacc[dn][0] * inv0, a1 = oacc[dn][1] * inv0;
        float a2 = oacc[dn][2] * inv1, a3 = oacc[dn][3] * inv1;
        __nv_bfloat162 h01 = __floats2bfloat162_rn(a0, a1);
        __nv_bfloat162 h23 = __floats2bfloat162_rn(a2, a3);
        float2 f01 = __bfloat1622float2(h01);
        float2 f23 = __bfloat1622float2(h23);
        __nv_bfloat162 lo01 = __floats2bfloat162_rn(a0 - f01.x, a1 - f01.y);
        __nv_bfloat162 lo23 = __floats2bfloat162_rn(a2 - f23.x, a3 - f23.y);
        *(__nv_bfloat162*)(yhi + r0 + dn * 8) = h01;
        *(__nv_bfloat162*)(ylo + r0 + dn * 8) = lo01;
        *(__nv_bfloat162*)(yhi + r1 + dn * 8) = h23;
        *(__nv_bfloat162*)(ylo + r1 + dn * 8) = lo23;
    }
}

// ---------------------------------------------------------------------------
// launch
// ---------------------------------------------------------------------------
extern "C" void kernel_launch(void* const* d_in, const int* in_sizes, int n_in,
                              void* d_out, int out_size) {
    const float* x     = (const float*)d_in[0];   // [2,2048,2048]
    const float* Wqkv  = (const float*)d_in[1];   // [6144,2048]
    const float* Wproj = (const float*)d_in[2];   // [2048,2048]
    float* out = (float*)d_out;                   // [2,2048,2048]

    float* qkv = nullptr;
    __nv_bfloat16 *qkvhi, *qkvlo, *xhi, *xlo, *whi, *wlo, *phi, *plo, *yhi, *ylo;
    cudaGetSymbolAddress((void**)&qkv, g_qkv);
    cudaGetSymbolAddress((void**)&qkvhi, g_qkvhi);
    cudaGetSymbolAddress((void**)&qkvlo, g_qkvlo);
    cudaGetSymbolAddress((void**)&xhi, g_xhi);
    cudaGetSymbolAddress((void**)&xlo, g_xlo);
    cudaGetSymbolAddress((void**)&whi, g_wqkvhi);
    cudaGetSymbolAddress((void**)&wlo, g_wqkvlo);
    cudaGetSymbolAddress((void**)&phi, g_wprojhi);
    cudaGetSymbolAddress((void**)&plo, g_wprojlo);
    cudaGetSymbolAddress((void**)&yhi, g_yhi);
    cudaGetSymbolAddress((void**)&ylo, g_ylo);

    cudaFuncSetAttribute(gemm_bf16x2, cudaFuncAttributeMaxDynamicSharedMemorySize,
                         GEMM_SMEM);
    cudaFuncSetAttribute(flash_attn_mma, cudaFuncAttributeMaxDynamicSharedMemorySize,
                         FLASH_SMEM);

    // 0) decompose inputs into bf16 hi/lo
    {
        int n4x = BT_ * C_ / 4;
        int n4w = QKV_C * C_ / 4;
        int n4p = C_ * C_ / 4;
        decompose_hi_lo<<<(n4x + 255) / 256, 256>>>(x, xhi, xlo, n4x);
        decompose_hi_lo<<<(n4w + 255) / 256, 256>>>(Wqkv, whi, wlo, n4w);
        decompose_hi_lo<<<(n4p + 255) / 256, 256>>>(Wproj, phi, plo, n4p);
    }
    // 1) qkv = x @ Wqkv^T  (HMMA bf16x2)
    {
        dim3 grid(QKV_C / GBN, BT_ / GBM);   // (48, 32)
        gemm_bf16x2<<<grid, 256, GEMM_SMEM>>>(xhi, xlo, whi, wlo, qkv,
                                              BT_, QKV_C, C_);
    }
    // 2) decompose qkv -> bf16 hi/lo for tensor-core attention
    {
        int n4 = BT_ * QKV_C / 4;
        decompose_hi_lo<<<(n4 + 255) / 256, 256>>>(qkv, qkvhi, qkvlo, n4);
    }
    // 3) tensor-core flash attention -> y hi/lo
    {
        dim3 grid(T_ / FQR, H_, B_);         // (16, 16, 2)
        flash_attn_mma<<<grid, 256, FLASH_SMEM>>>(qkvhi, qkvlo, yhi, ylo);
    }
    // 4) out = y @ Wproj^T  (HMMA bf16x2)
    {
        dim3 grid(C_ / GBN, BT_ / GBM);      // (16, 32)
        gemm_bf16x2<<<grid, 256, GEMM_SMEM>>>(yhi, ylo, phi, plo, out,
                                              BT_, C_, C_);
    }
}

// round 16
// speedup vs baseline: 1.0715x; 1.0715x over previous
#include <cuda_runtime.h>
#include <cuda_bf16.h>
#include <cstdint>

// Shapes (fixed for this problem)
#define B_  2
#define T_  2048
#define C_  2048          // d_model
#define H_  16
#define DH_ 128           // head dim
#define BT_ (B_ * T_)     // 4096 rows
#define QKV_C (3 * C_)    // 6144
#define GK 2048           // GEMM K (both projections)

// ---------------------------------------------------------------------------
// Scratch (device globals — no allocation)
// ---------------------------------------------------------------------------
__device__ __nv_bfloat16 g_qkvhi[(size_t)BT_ * QKV_C];       // 48 MB
__device__ __nv_bfloat16 g_qkvlo[(size_t)BT_ * QKV_C];       // 48 MB
__device__ __nv_bfloat16 g_xhi[(size_t)BT_ * C_];
__device__ __nv_bfloat16 g_xlo[(size_t)BT_ * C_];
__device__ __nv_bfloat16 g_wqkvhi[(size_t)QKV_C * C_];
__device__ __nv_bfloat16 g_wqkvlo[(size_t)QKV_C * C_];
__device__ __nv_bfloat16 g_wprojhi[(size_t)C_ * C_];
__device__ __nv_bfloat16 g_wprojlo[(size_t)C_ * C_];
__device__ __nv_bfloat16 g_yhi[(size_t)BT_ * C_];
__device__ __nv_bfloat16 g_ylo[(size_t)BT_ * C_];

// ---------------------------------------------------------------------------
// PTX helpers (portable sm_80-level ISA only — harness emits compute_103)
// ---------------------------------------------------------------------------
__device__ __forceinline__ uint32_t smem_u32(const void* p) {
    uint32_t a;
    asm("{ .reg .u64 t; cvta.to.shared.u64 t, %1; cvt.u32.u64 %0, t; }"
        : "=r"(a) : "l"(p));
    return a;
}

#define CP16(dst, src) \
    asm volatile("cp.async.cg.shared.global [%0], [%1], 16;" \
                 :: "r"(dst), "l"(src) : "memory")
#define CP_COMMIT() asm volatile("cp.async.commit_group;" ::: "memory")

#define LDSM4(r, addr) \
    asm volatile("ldmatrix.sync.aligned.m8n8.x4.shared.b16 {%0,%1,%2,%3}, [%4];" \
                 : "=r"((r)[0]), "=r"((r)[1]), "=r"((r)[2]), "=r"((r)[3]) \
                 : "r"(addr))

#define LDSM4T(r, addr) \
    asm volatile("ldmatrix.sync.aligned.m8n8.x4.trans.shared.b16 {%0,%1,%2,%3}, [%4];" \
                 : "=r"((r)[0]), "=r"((r)[1]), "=r"((r)[2]), "=r"((r)[3]) \
                 : "r"(addr))

#define LDSM2(r, addr) \
    asm volatile("ldmatrix.sync.aligned.m8n8.x2.shared.b16 {%0,%1}, [%2];" \
                 : "=r"((r)[0]), "=r"((r)[1]) \
                 : "r"(addr))

#define MMA_BF16(d, a, b) \
    asm volatile("mma.sync.aligned.m16n8k16.row.col.f32.bf16.bf16.f32 " \
                 "{%0,%1,%2,%3}, {%4,%5,%6,%7}, {%8,%9}, {%0,%1,%2,%3};" \
                 : "+f"((d)[0]), "+f"((d)[1]), "+f"((d)[2]), "+f"((d)[3]) \
                 : "r"((a)[0]), "r"((a)[1]), "r"((a)[2]), "r"((a)[3]), \
                   "r"((b)[0]), "r"((b)[1]))

// fast exp2 for x <= 0: degree-5 poly, rel err < 1e-4, no MUFU
__device__ __forceinline__ float exp2_fast(float x) {
    x = fmaxf(x, -80.f);
    float fl = floorf(x);
    float fr = x - fl;
    float p = fmaf(fr, 0.00133335581f, 0.00961812910f);
    p = fmaf(fr, p, 0.0555041089f);
    p = fmaf(fr, p, 0.240226512f);
    p = fmaf(fr, p, 0.693147182f);
    p = fmaf(fr, p, 1.0f);
    int e = (int)fl;
    return __int_as_float((e + 127) << 23) * p;
}

// ---------------------------------------------------------------------------
// Decompose fp32 -> bf16 hi + bf16 lo (elementwise, float4-vectorized)
// ---------------------------------------------------------------------------
__global__ void decompose_hi_lo(const float* __restrict__ in,
                                __nv_bfloat16* __restrict__ hi,
                                __nv_bfloat16* __restrict__ lo, int n4) {
    int i = blockIdx.x * 256 + threadIdx.x;
    if (i >= n4) return;
    float4 v = ((const float4*)in)[i];
    __nv_bfloat162 h0 = __floats2bfloat162_rn(v.x, v.y);
    __nv_bfloat162 h1 = __floats2bfloat162_rn(v.z, v.w);
    float2 f0 = __bfloat1622float2(h0);
    float2 f1 = __bfloat1622float2(h1);
    __nv_bfloat162 l0 = __floats2bfloat162_rn(v.x - f0.x, v.y - f0.y);
    __nv_bfloat162 l1 = __floats2bfloat162_rn(v.z - f1.x, v.w - f1.y);
    ((__nv_bfloat162*)hi)[i * 2 + 0] = h0;
    ((__nv_bfloat162*)hi)[i * 2 + 1] = h1;
    ((__nv_bfloat162*)lo)[i * 2 + 0] = l0;
    ((__nv_bfloat162*)lo)[i * 2 + 1] = l1;
}

// ---------------------------------------------------------------------------
// HMMA GEMM: C[M,N] = (Ahi+Alo)[M,K] @ (Bhi+Blo)[N,K]^T, K = 2048.
// CTA tile 128x128, BK=32, 8 warps (2x4), warp tile 64x32, 3 passes.
// 2-stage cp.async pipeline, __launch_bounds__(256,2) -> 2 CTAs/SM.
// SPLIT=true: write bf16 hi/lo outputs (fused decompose); else fp32 C.
// ---------------------------------------------------------------------------
#define GBM 128
#define GBN 128
#define GBK 32
#define ASTR 40                              // bf16 elems per smem row (80 B)
#define ARR_B (128 * ASTR * 2)               // 10240 B per array
#define STAGE_B (4 * ARR_B)                  // 40960 B (Ahi, Alo, Bhi, Blo)
#define GEMM_SMEM (2 * STAGE_B)              // 81920 B

template<bool SPLIT>
__global__ __launch_bounds__(256, 2)
void gemm_bf16x2(const __nv_bfloat16* __restrict__ Ahi,
                 const __nv_bfloat16* __restrict__ Alo,
                 const __nv_bfloat16* __restrict__ Bhi,
                 const __nv_bfloat16* __restrict__ Blo,
                 float* __restrict__ C,
                 __nv_bfloat16* __restrict__ Chi,
                 __nv_bfloat16* __restrict__ Clo,
                 int M, int N) {
    extern __shared__ char gsm[];
    const uint32_t sbase = smem_u32(gsm);
    const int tid = threadIdx.x;
    const int wid = tid >> 5, lid = tid & 31;
    const int warp_m = wid >> 2;
    const int warp_n = wid & 3;
    const int bm = blockIdx.y * GBM;
    const int bn = blockIdx.x * GBN;

    // ---- cp.async geometry (strength-reduced; K constexpr) ----
    const __nv_bfloat16* gb[4] = {
        Ahi + (size_t)bm * GK, Alo + (size_t)bm * GK,
        Bhi + (size_t)bn * GK, Blo + (size_t)bn * GK };
    const uint32_t grow = (uint32_t)(tid >> 2) * GK + (uint32_t)(tid & 3) * 8;
    const uint32_t drow = (uint32_t)(tid >> 2) * (ASTR * 2) + (uint32_t)(tid & 3) * 16;

    // ---- ldmatrix per-lane offsets ----
    const int r8 = lid & 7;
    uint32_t aoff[4], boff[4];
    #pragma unroll
    for (int mi = 0; mi < 4; mi++)
        aoff[mi] = (uint32_t)((warp_m * 64 + mi * 16 + r8 + ((lid >> 3) & 1) * 8)
                              * (ASTR * 2) + ((lid >> 4) & 1) * 16);
    #pragma unroll
    for (int ni = 0; ni < 4; ni++)
        boff[ni] = (uint32_t)((warp_n * 32 + ni * 8 + r8)
                              * (ASTR * 2) + ((lid >> 3) & 1) * 16);

    float acc[4][4][4];
    #pragma unroll
    for (int mi = 0; mi < 4; mi++)
        #pragma unroll
        for (int ni = 0; ni < 4; ni++)
            #pragma unroll
            for (int e = 0; e < 4; e++) acc[mi][ni][e] = 0.f;

    const int nch = GK / GBK;                // 64

    // ---- prologue: stage 0 ----
    {
        #pragma unroll
        for (int i = 0; i < 8; i++)
            CP16(sbase + (i >> 1) * ARR_B + (i & 1) * (64 * ASTR * 2) + drow,
                 gb[i >> 1] + (i & 1) * (64 * GK) + grow);
        CP_COMMIT();
    }

    for (int c = 0; c < nch; c++) {
        asm volatile("cp.async.wait_group 0;" ::: "memory");
        __syncthreads();

        if (c + 1 < nch) {
            uint32_t sb = sbase + ((c + 1) & 1) * STAGE_B;
            uint32_t ko = (uint32_t)(c + 1) * GBK;
            #pragma unroll
            for (int i = 0; i < 8; i++)
                CP16(sb + (i >> 1) * ARR_B + (i & 1) * (64 * ASTR * 2) + drow,
                     gb[i >> 1] + (i & 1) * (64 * GK) + grow + ko);
            CP_COMMIT();
        }

        const uint32_t sb = sbase + (c & 1) * STAGE_B;
        #pragma unroll
        for (int ks = 0; ks < 2; ks++) {
            uint32_t ah[4][4], al[4][4];
            #pragma unroll
            for (int mi = 0; mi < 4; mi++) {
                LDSM4(ah[mi], sb + 0 * ARR_B + aoff[mi] + ks * 32);
                LDSM4(al[mi], sb + 1 * ARR_B + aoff[mi] + ks * 32);
            }
            #pragma unroll
            for (int ni = 0; ni < 4; ni++) {
                uint32_t bh[2], bl[2];
                LDSM2(bh, sb + 2 * ARR_B + boff[ni] + ks * 32);
                LDSM2(bl, sb + 3 * ARR_B + boff[ni] + ks * 32);
                #pragma unroll
                for (int mi = 0; mi < 4; mi++)
                    MMA_BF16(acc[mi][ni], ah[mi], bh);       // hi*hi
                #pragma unroll
                for (int mi = 0; mi < 4; mi++)
                    MMA_BF16(acc[mi][ni], ah[mi], bl);       // hi*lo
                #pragma unroll
                for (int mi = 0; mi < 4; mi++)
                    MMA_BF16(acc[mi][ni], al[mi], bh);       // lo*hi
            }
        }
    }

    // ---- epilogue ----
    const int g = lid >> 2, t4 = lid & 3;
    #pragma unroll
    for (int mi = 0; mi < 4; mi++) {
        int row = bm + warp_m * 64 + mi * 16 + g;
        #pragma unroll
        for (int ni = 0; ni < 4; ni++) {
            int col = bn + warp_n * 32 + ni * 8 + 2 * t4;
            if (SPLIT) {
                size_t i0 = (size_t)row * N + col;
                size_t i1 = (size_t)(row + 8) * N + col;
                __nv_bfloat162 h01 = __floats2bfloat162_rn(acc[mi][ni][0], acc[mi][ni][1]);
                __nv_bfloat162 h23 = __floats2bfloat162_rn(acc[mi][ni][2], acc[mi][ni][3]);
                float2 f01 = __bfloat1622float2(h01);
                float2 f23 = __bfloat1622float2(h23);
                __nv_bfloat162 l01 = __floats2bfloat162_rn(acc[mi][ni][0] - f01.x,
                                                           acc[mi][ni][1] - f01.y);
                __nv_bfloat162 l23 = __floats2bfloat162_rn(acc[mi][ni][2] - f23.x,
                                                           acc[mi][ni][3] - f23.y);
                *(__nv_bfloat162*)(Chi + i0) = h01;
                *(__nv_bfloat162*)(Clo + i0) = l01;
                *(__nv_bfloat162*)(Chi + i1) = h23;
                *(__nv_bfloat162*)(Clo + i1) = l23;
            } else {
                *(float2*)(C + (size_t)row * N + col) =
                    make_float2(acc[mi][ni][0], acc[mi][ni][1]);
                *(float2*)(C + (size_t)(row + 8) * N + col) =
                    make_float2(acc[mi][ni][2], acc[mi][ni][3]);
            }
        }
    }
}

// ---------------------------------------------------------------------------
// Tensor-core flash attention (causal), bf16 hi/lo 3-pass for QK^T and PV.
// (unchanged from R13)
// ---------------------------------------------------------------------------
#define FQR 128
#define FKR 64
#define FSTR_B 272
#define FARR_B (FKR * FSTR_B)
#define FSTAGE_B (4 * FARR_B)
#define FLASH_SMEM (2 * FSTAGE_B)

#define CLOG2 0.12751744f                // (1/sqrt(128)) * log2(e)

__global__ __launch_bounds__(256, 1)
void flash_attn_mma(const __nv_bfloat16* __restrict__ qkvhi,
                    const __nv_bfloat16* __restrict__ qkvlo,
                    __nv_bfloat16* __restrict__ yhi,
                    __nv_bfloat16* __restrict__ ylo) {
    extern __shared__ char fsmc[];
    const uint32_t sb0 = smem_u32(fsmc);
    const int qt = gridDim.x - 1 - blockIdx.x;   // big tiles first
    const int h = blockIdx.y, b = blockIdx.z;
    const int tid = threadIdx.x, wid = tid >> 5, lid = tid & 31;
    const int t8 = lid >> 3, l7 = lid & 7;

    const size_t rowbase = (size_t)(b * T_) * QKV_C + h * DH_;

    // ---- load Q tile (hi/lo) into stage-0 area ----
    #pragma unroll
    for (int i = 0; i < 16; i++) {
        int cid = tid + i * 256;
        int arr = cid >> 11;
        int rem = cid & 2047;
        int row = rem >> 4, q = rem & 15;
        const __nv_bfloat16* s = (arr ? qkvlo : qkvhi)
            + rowbase + (size_t)(qt * FQR + row) * QKV_C + q * 8;
        CP16(sb0 + arr * 34816 + row * FSTR_B + q * 16, s);
    }
    CP_COMMIT();
    asm volatile("cp.async.wait_group 0;" ::: "memory");
    __syncthreads();

    // ---- Q fragments -> registers ----
    uint32_t qh[8][4], qlr[8][4];
    {
        uint32_t lanebase = (uint32_t)((wid * 16 + (t8 & 1) * 8 + l7) * FSTR_B
                                       + (t8 >> 1) * 16);
        #pragma unroll
        for (int kk = 0; kk < 8; kk++) {
            LDSM4(qh[kk],  sb0 + lanebase + kk * 32);
            LDSM4(qlr[kk], sb0 + 34816 + lanebase + kk * 32);
        }
    }
    __syncthreads();

    auto issue_tile = [&](int kt, uint32_t stg) {
        #pragma unroll
        for (int i = 0; i < 16; i++) {
            int cid = tid + i * 256;
            int arr = cid >> 10;
            int rem = cid & 1023;
            int row = rem >> 4, q = rem & 15;
            const __nv_bfloat16* base = (arr & 1) ? qkvlo : qkvhi;
            int koff = (arr >> 1) ? 2 * C_ : C_;
            const __nv_bfloat16* s = base + rowbase + koff
                + (size_t)(kt * FKR + row) * QKV_C + q * 8;
            CP16(stg + arr * FARR_B + row * FSTR_B + q * 16, s);
        }
        CP_COMMIT();
    };

    float oacc[16][4];
    #pragma unroll
    for (int dn = 0; dn < 16; dn++)
        #pragma unroll
        for (int e = 0; e < 4; e++) oacc[dn][e] = 0.f;
    float m0 = -1e30f, m1 = -1e30f, l0 = 0.f, l1 = 0.f;

    const int g = lid >> 2;
    const int qr0 = qt * FQR + wid * 16 + g;
    const int qr1 = qr0 + 8;
    const int wrmax = qt * FQR + wid * 16 + 15;
    const uint32_t kbase = (uint32_t)(((t8 >> 1) * 8 + l7) * FSTR_B + (t8 & 1) * 16);
    const uint32_t vbase = (uint32_t)(((t8 & 1) * 8 + l7) * FSTR_B + (t8 >> 1) * 16);

    const int nkt = 2 * qt + 2;
    issue_tile(0, sb0);

    for (int kt = 0; kt < nkt; kt++) {
        const uint32_t stage = sb0 + (kt & 1) * FSTAGE_B;
        if (kt + 1 < nkt) {
            issue_tile(kt + 1, sb0 + ((kt + 1) & 1) * FSTAGE_B);
            asm volatile("cp.async.wait_group 1;" ::: "memory");
        } else {
            asm volatile("cp.async.wait_group 0;" ::: "memory");
        }
        __syncthreads();

        if (kt * FKR <= wrmax) {
            float sacc[8][4];
            #pragma unroll
            for (int nt = 0; nt < 8; nt++)
                #pragma unroll
                for (int e = 0; e < 4; e++) sacc[nt][e] = 0.f;

            const uint32_t Kh = stage, Kl = stage + FARR_B;
            #pragma unroll
            for (int kk = 0; kk < 8; kk++) {
                #pragma unroll
                for (int ntp = 0; ntp < 4; ntp++) {
                    uint32_t khf[4], klf[4];
                    LDSM4(khf, Kh + ntp * (16 * FSTR_B) + kbase + kk * 32);
                    LDSM4(klf, Kl + ntp * (16 * FSTR_B) + kbase + kk * 32);
                    MMA_BF16(sacc[2 * ntp],     qh[kk],  &khf[0]);
                    MMA_BF16(sacc[2 * ntp],     qh[kk],  &klf[0]);
                    MMA_BF16(sacc[2 * ntp],     qlr[kk], &khf[0]);
                    MMA_BF16(sacc[2 * ntp + 1], qh[kk],  &khf[2]);
                    MMA_BF16(sacc[2 * ntp + 1], qh[kk],  &klf[2]);
                    MMA_BF16(sacc[2 * ntp + 1], qlr[kk], &khf[2]);
                }
            }

            if (kt * FKR + FKR - 1 > qr0) {
                #pragma unroll
                for (int nt = 0; nt < 8; nt++) {
                    int col = kt * FKR + nt * 8 + 2 * (lid & 3);
                    if (col     > qr0) sacc[nt][0] = -1e30f;
                    if (col + 1 > qr0) sacc[nt][1] = -1e30f;
                    if (col     > qr1) sacc[nt][2] = -1e30f;
                    if (col + 1 > qr1) sacc[nt][3] = -1e30f;
                }
            }

            float rm0 = -1e30f, rm1 = -1e30f;
            #pragma unroll
            for (int nt = 0; nt < 8; nt++) {
                rm0 = fmaxf(rm0, fmaxf(sacc[nt][0], sacc[nt][1]));
                rm1 = fmaxf(rm1, fmaxf(sacc[nt][2], sacc[nt][3]));
            }
            #pragma unroll
            for (int d = 1; d < 4; d <<= 1) {
                rm0 = fmaxf(rm0, __shfl_xor_sync(0xFFFFFFFFu, rm0, d));
                rm1 = fmaxf(rm1, __shfl_xor_sync(0xFFFFFFFFu, rm1, d));
            }
            float m0n = fmaxf(m0, rm0), m1n = fmaxf(m1, rm1);
            float rs0 = exp2_fast((m0 - m0n) * CLOG2);
            float rs1 = exp2_fast((m1 - m1n) * CLOG2);
            m0 = m0n; m1 = m1n;

            float ls0 = 0.f, ls1 = 0.f;
            uint32_t pha[8][2], pla[8][2];
            #pragma unroll
            for (int nt = 0; nt < 8; nt++) {
                float p0 = exp2_fast((sacc[nt][0] - m0) * CLOG2);
                float p1 = exp2_fast((sacc[nt][1] - m0) * CLOG2);
                float p2 = exp2_fast((sacc[nt][2] - m1) * CLOG2);
                float p3 = exp2_fast((sacc[nt][3] - m1) * CLOG2);
                ls0 += p0 + p1; ls1 += p2 + p3;
                __nv_bfloat162 h01 = __floats2bfloat162_rn(p0, p1);
                __nv_bfloat162 h23 = __floats2bfloat162_rn(p2, p3);
                float2 f01 = __bfloat1622float2(h01);
                float2 f23 = __bfloat1622float2(h23);
                __nv_bfloat162 lo01 = __floats2bfloat162_rn(p0 - f01.x, p1 - f01.y);
                __nv_bfloat162 lo23 = __floats2bfloat162_rn(p2 - f23.x, p3 - f23.y);
                pha[nt][0] = *(uint32_t*)&h01;  pha[nt][1] = *(uint32_t*)&h23;
                pla[nt][0] = *(uint32_t*)&lo01; pla[nt][1] = *(uint32_t*)&lo23;
            }
            #pragma unroll
            for (int d = 1; d < 4; d <<= 1) {
                ls0 += __shfl_xor_sync(0xFFFFFFFFu, ls0, d);
                ls1 += __shfl_xor_sync(0xFFFFFFFFu, ls1, d);
            }
            l0 = l0 * rs0 + ls0;
            l1 = l1 * rs1 + ls1;

            #pragma unroll
            for (int dn = 0; dn < 16; dn++) {
                oacc[dn][0] *= rs0; oacc[dn][1] *= rs0;
                oacc[dn][2] *= rs1; oacc[dn][3] *= rs1;
            }

            const uint32_t Vh = stage + 2 * FARR_B, Vl = stage + 3 * FARR_B;
            #pragma unroll
            for (int ks = 0; ks < 4; ks++) {
                uint32_t aH[4] = {pha[2 * ks][0], pha[2 * ks][1],
                                  pha[2 * ks + 1][0], pha[2 * ks + 1][1]};
                uint32_t aL[4] = {pla[2 * ks][0], pla[2 * ks][1],
                                  pla[2 * ks + 1][0], pla[2 * ks + 1][1]};
                #pragma unroll
                for (int dtp = 0; dtp < 8; dtp++) {
                    uint32_t vhf[4], vlf[4];
                    LDSM4T(vhf, Vh + ks * (16 * FSTR_B) + vbase + dtp * 32);
                    LDSM4T(vlf, Vl + ks * (16 * FSTR_B) + vbase + dtp * 32);
                    MMA_BF16(oacc[2 * dtp],     aH, &vhf[0]);
                    MMA_BF16(oacc[2 * dtp],     aL, &vhf[0]);
                    MMA_BF16(oacc[2 * dtp],     aH, &vlf[0]);
                    MMA_BF16(oacc[2 * dtp + 1], aH, &vhf[2]);
                    MMA_BF16(oacc[2 * dtp + 1], aL, &vhf[2]);
                    MMA_BF16(oacc[2 * dtp + 1], aH, &vlf[2]);
                }
            }
        }
        __syncthreads();
    }

    // ---- epilogue: normalize, decompose to bf16 hi/lo, store ----
    float inv0 = 1.f / l0, inv1 = 1.f / l1;
    size_t r0 = (size_t)(b * T_ + qt * FQR + wid * 16 + g) * C_
                + h * DH_ + 2 * (lid & 3);
    size_t r1 = r0 + 8 * (size_t)C_;
    #pragma unroll
    for (int dn = 0; dn < 16; dn++) {
        float a0 = oacc[dn][0] * inv0, a1 = oacc[dn][1] * inv0;
        float a2 = oacc[dn][2] * inv1, a3 = oacc[dn][3] * inv1;
        __nv_bfloat162 h01 = __floats2bfloat162_rn(a0, a1);
        __nv_bfloat162 h23 = __floats2bfloat162_rn(a2, a3);
        float2 f01 = __bfloat1622float2(h01);
        float2 f23 = __bfloat1622float2(h23);
        __nv_bfloat162 lo01 = __floats2bfloat162_rn(a0 - f01.x, a1 - f01.y);
        __nv_bfloat162 lo23 = __floats2bfloat162_rn(a2 - f23.x, a3 - f23.y);
        *(__nv_bfloat162*)(yhi + r0 + dn * 8) = h01;
        *(__nv_bfloat162*)(ylo + r0 + dn * 8) = lo01;
        *(__nv_bfloat162*)(yhi + r1 + dn * 8) = h23;
        *(__nv_bfloat162*)(ylo + r1 + dn * 8) = lo23;
    }
}

// ---------------------------------------------------------------------------
// launch
// ---------------------------------------------------------------------------
extern "C" void kernel_launch(void* const* d_in, const int* in_sizes, int n_in,
                              void* d_out, int out_size) {
    const float* x     = (const float*)d_in[0];   // [2,2048,2048]
    const float* Wqkv  = (const float*)d_in[1];   // [6144,2048]
    const float* Wproj = (const float*)d_in[2];   // [2048,2048]
    float* out = (float*)d_out;                   // [2,2048,2048]

    __nv_bfloat16 *qkvhi, *qkvlo, *xhi, *xlo, *whi, *wlo, *phi, *plo, *yhi, *ylo;
    cudaGetSymbolAddress((void**)&qkvhi, g_qkvhi);
    cudaGetSymbolAddress((void**)&qkvlo, g_qkvlo);
    cudaGetSymbolAddress((void**)&xhi, g_xhi);
    cudaGetSymbolAddress((void**)&xlo, g_xlo);
    cudaGetSymbolAddress((void**)&whi, g_wqkvhi);
    cudaGetSymbolAddress((void**)&wlo, g_wqkvlo);
    cudaGetSymbolAddress((void**)&phi, g_wprojhi);
    cudaGetSymbolAddress((void**)&plo, g_wprojlo);
    cudaGetSymbolAddress((void**)&yhi, g_yhi);
    cudaGetSymbolAddress((void**)&ylo, g_ylo);

    cudaFuncSetAttribute(gemm_bf16x2<true>,
                         cudaFuncAttributeMaxDynamicSharedMemorySize, GEMM_SMEM);
    cudaFuncSetAttribute(gemm_bf16x2<false>,
                         cudaFuncAttributeMaxDynamicSharedMemorySize, GEMM_SMEM);
    cudaFuncSetAttribute(flash_attn_mma,
                         cudaFuncAttributeMaxDynamicSharedMemorySize, FLASH_SMEM);

    // 0) decompose inputs into bf16 hi/lo
    {
        int n4x = BT_ * C_ / 4;
        int n4w = QKV_C * C_ / 4;
        int n4p = C_ * C_ / 4;
        decompose_hi_lo<<<(n4x + 255) / 256, 256>>>(x, xhi, xlo, n4x);
        decompose_hi_lo<<<(n4w + 255) / 256, 256>>>(Wqkv, whi, wlo, n4w);
        decompose_hi_lo<<<(n4p + 255) / 256, 256>>>(Wproj, phi, plo, n4p);
    }
    // 1) qkv(hi/lo) = x @ Wqkv^T  (HMMA bf16x2, fused hi/lo epilogue)
    {
        dim3 grid(QKV_C / GBN, BT_ / GBM);   // (48, 32)
        gemm_bf16x2<true><<<grid, 256, GEMM_SMEM>>>(xhi, xlo, whi, wlo,
                                                    nullptr, qkvhi, qkvlo,
                                                    BT_, QKV_C);
    }
    // 2) tensor-core flash attention -> y hi/lo
    {
        dim3 grid(T_ / FQR, H_, B_);         // (16, 16, 2)
        flash_attn_mma<<<grid, 256, FLASH_SMEM>>>(qkvhi, qkvlo, yhi, ylo);
    }
    // 3) out = y @ Wproj^T  (HMMA bf16x2, fp32 out)
    {
        dim3 grid(C_ / GBN, BT_ / GBM);      // (16, 32)
        gemm_bf16x2<false><<<grid, 256, GEMM_SMEM>>>(yhi, ylo, phi, plo,
                                                     out, nullptr, nullptr,
                                                     BT_, C_);
    }
}